// round 4
// baseline (speedup 1.0000x reference)
#include <cuda_runtime.h>
#include <cuda_bf16.h>
#include <cstdint>
#include <cstring>

// ---------------- constants ----------------
constexpr int NP = 8192;
constexpr int WTOT = 23592960;
constexpr int PER_BLK_W = 737280;
constexpr size_t WP_PER_BLK = 2949120;
constexpr size_t MP_PER_BLK = 147456;

// ---------------- device scratch ----------------
__device__ char g_wpc[32 * WP_PER_BLK];
__device__ char g_mpc[32 * MP_PER_BLK];
__device__ float g_Xa[NP * 192], g_Xb[NP * 192];
__device__ __nv_bfloat16 g_XaH[NP * 192], g_XaL[NP * 192];
__device__ __nv_bfloat16 g_XbH[NP * 192], g_XbL[NP * 192];
__device__ __nv_bfloat16 g_T1H[NP * 128], g_T1L[NP * 128];
__device__ __nv_bfloat16 g_T2H[NP * 128], g_T2L[NP * 128];

// ---------------- helpers ----------------
__device__ __forceinline__ uint32_t smem_u32(const void* p) {
    uint32_t a;
    asm("{ .reg .u64 t; cvta.to.shared.u64 t, %1; cvt.u32.u64 %0, t; }" : "=r"(a) : "l"(p));
    return a;
}
__device__ __forceinline__ unsigned short f2bf(float v) {
    __nv_bfloat16 b = __float2bfloat16(v);
    unsigned short u; memcpy(&u, &b, 2);
    return u;
}
__device__ __forceinline__ float bf2f(unsigned short u) {
    __nv_bfloat16 b; memcpy(&b, &u, 2);
    return __bfloat162float(b);
}
__device__ __forceinline__ void ldm4(uint32_t* r, uint32_t addr) {
    asm volatile("ldmatrix.sync.aligned.m8n8.x4.shared.b16 {%0,%1,%2,%3}, [%4];"
        : "=r"(r[0]), "=r"(r[1]), "=r"(r[2]), "=r"(r[3]) : "r"(addr));
}
__device__ __forceinline__ void ldm2(uint32_t* r, uint32_t addr) {
    asm volatile("ldmatrix.sync.aligned.m8n8.x2.shared.b16 {%0,%1}, [%2];"
        : "=r"(r[0]), "=r"(r[1]) : "r"(addr));
}
__device__ __forceinline__ void mma16816(float* d, const uint32_t* a, uint32_t b0, uint32_t b1) {
    asm volatile("mma.sync.aligned.m16n8k16.row.col.f32.bf16.bf16.f32 "
        "{%0,%1,%2,%3},{%4,%5,%6,%7},{%8,%9},{%0,%1,%2,%3};"
        : "+f"(d[0]), "+f"(d[1]), "+f"(d[2]), "+f"(d[3])
        : "r"(a[0]), "r"(a[1]), "r"(a[2]), "r"(a[3]), "r"(b0), "r"(b1));
}
__device__ __forceinline__ void cpa16(uint32_t dst, const void* src, uint32_t srcsz) {
    asm volatile("cp.async.cg.shared.global [%0], [%1], 16, %2;"
        :: "r"(dst), "l"(src), "r"(srcsz) : "memory");
}
#define CP_COMMIT() asm volatile("cp.async.commit_group;" ::: "memory")
#define CP_WAIT1()  asm volatile("cp.async.wait_group 1;" ::: "memory")
#define CP_WAIT0()  asm volatile("cp.async.wait_group 0;" ::: "memory")

// ---------------- weight prepack (convs), dst-indexed ----------------
// per conv j: units of (OC*128) bytes keyed by tap*(ic/32)+chunk:
//   hi block [OC][32] bf16 then lo block [OC][32] bf16.
__global__ void k_wp(const float* __restrict__ wf) {
    int idx = blockIdx.x * 256 + threadIdx.x;
    if (idx >= WTOT) return;
    int blk = idx / PER_BLK_W;
    int r = idx - blk * PER_BLK_W;
    const int starts[6] = {0, 110592, 258048, 368640, 479232, 626688};
    const size_t pre[6] = {0, 442368, 1032192, 1474560, 1916928, 2506752};
    int j = 0;
#pragma unroll
    for (int t = 1; t < 6; t++) if (r >= starts[t]) j = t;
    int off = r - starts[j];
    int oc = ((j % 3) == 2) ? 96 : 128;
    int ic = ((j % 3) == 0) ? 96 : 128;
    int unitE = oc * 32;
    int u = off / unitE;
    int wi = off - u * unitE;
    int o = wi >> 5, cl = wi & 31;
    int nch = ic >> 5;
    int tap = u / nch, chk = u - tap * nch;
    int c = chk * 32 + cl;
    float v = wf[(size_t)blk * PER_BLK_W + starts[j] + (size_t)(o * ic + c) * 9 + tap];
    unsigned short hb = f2bf(v);
    unsigned short lb = f2bf(v - bf2f(hb));
    size_t base = (size_t)blk * WP_PER_BLK + pre[j] + (size_t)u * (oc * 128);
    *(unsigned short*)(g_wpc + base + (size_t)wi * 2) = hb;
    *(unsigned short*)(g_wpc + base + (size_t)oc * 64 + (size_t)wi * 2) = lb;
}

// ---------------- mixing prepack ----------------
__global__ void k_mp(const float* __restrict__ m) {
    int idx = blockIdx.x * 256 + threadIdx.x;
    if (idx >= 32 * 36864) return;
    int blk = idx / 36864;
    int r = idx - blk * 36864;
    int u = r / 6144;
    int wi = r - u * 6144;
    int o = wi >> 5, cl = wi & 31;
    int c = u * 32 + cl;
    float v = m[(size_t)blk * 36864 + o * 192 + c];
    unsigned short hb = f2bf(v);
    unsigned short lb = f2bf(v - bf2f(hb));
    size_t base = (size_t)blk * MP_PER_BLK + (size_t)u * 24576;
    *(unsigned short*)(g_mpc + base + (size_t)wi * 2) = hb;
    *(unsigned short*)(g_mpc + base + 12288 + (size_t)wi * 2) = lb;
}

// ---------------- normalize + permute + space_to_depth -> NHWC ----------------
__global__ void k_pre(const float* __restrict__ x, const float* __restrict__ mu,
                      const float* __restrict__ sigma, const int* __restrict__ perm,
                      float* __restrict__ Xo, __nv_bfloat16* __restrict__ XoH,
                      __nv_bfloat16* __restrict__ XoL) {
    int idx = blockIdx.x * 256 + threadIdx.x;
    if (idx >= NP * 192) return;
    int ch = idx % 192;
    int p = idx / 192;
    int w = p & 31, h = (p >> 5) & 31, b = p >> 10;
    int c = ch >> 6, r = ch & 63;
    int bi = r >> 3, bj = r & 7;
    int flat = (h * 8 + bi) * 256 + (w * 8 + bj);
    int src = perm[c * 65536 + flat];
    float v = (x[(b * 3 + c) * 65536 + src] - mu[c]) / sigma[c];
    Xo[idx] = v;
    unsigned short hb = f2bf(v);
    XoH[idx] = *(__nv_bfloat16*)&hb;
    unsigned short lb = f2bf(v - bf2f(hb));
    XoL[idx] = *(__nv_bfloat16*)&lb;
}

// ---------------- final NHWC -> NCHW ----------------
__global__ void k_post(const float* __restrict__ X, float* __restrict__ out) {
    int idx = blockIdx.x * 256 + threadIdx.x;
    if (idx >= NP * 192) return;
    int w = idx & 31;
    int h = (idx >> 5) & 31;
    int ch = (idx >> 10) % 192;
    int b = idx / (192 * 1024);
    out[idx] = X[(((b * 32 + h) * 32 + w) * 192) + ch];
}

// ---------------- warp-mma bf16x3 implicit-GEMM conv, cp.async pipelined ----------------
// CTA = 64 positions x OCT columns (OCT-wide slice of OC at nofs).
// 8 warps: wm = wid&1 (two m16 tiles each), wn = wid>>1 (OCT/4 cols each).
template <int IC, int OC, int OCT, int KS, bool RELU, bool ADDIN>
__global__ __launch_bounds__(256, 2) void k_mma(
    const __nv_bfloat16* __restrict__ inH, const __nv_bfloat16* __restrict__ inL,
    int in_stride,
    const char* __restrict__ wp,
    const float* __restrict__ bias,
    const float* __restrict__ addp, int add_stride,
    float* __restrict__ out,
    __nv_bfloat16* __restrict__ outH, __nv_bfloat16* __restrict__ outL,
    int out_stride)
{
    constexpr int NCH = IC / 32;
    constexpr int NST = KS * KS * NCH;
    constexpr int NT = OCT / 32;         // n8-tiles per warp (1 or 2)
    constexpr int NSPL = OC / OCT;
    constexpr int PH = KS / 2;
    constexpr int LDA = 40;              // bf16 row stride (80 B)
    constexpr int unitB = OC * 128;

    __shared__ __align__(16) unsigned short Ah[2][64][LDA], Al[2][64][LDA];
    __shared__ __align__(16) unsigned short Bh[2][OCT][LDA], Bl[2][OCT][LDA];

    const int tid = threadIdx.x;
    const int wid = tid >> 5, lane = tid & 31;
    const int wm = wid & 1, wn = wid >> 1;
    const int bx = blockIdx.x;
    const int tile = bx / NSPL;
    const int nofs = (bx - tile * NSPL) * OCT;
    const int p0 = tile * 64;
    const int b = p0 >> 10;
    const int h0 = (p0 >> 5) & 31;

    // A staging map: thread -> (row 0..63, 8-channel quad)
    const int ar = tid >> 2;
    const int ac = (tid & 3) * 8;
    const int ah_ = h0 + (ar >> 5);
    const int aw = ar & 31;

    float acc[2][NT][4];
#pragma unroll
    for (int i = 0; i < 2; i++)
#pragma unroll
        for (int j = 0; j < NT; j++)
#pragma unroll
            for (int q = 0; q < 4; q++) acc[i][j][q] = 0.f;

    // ---- stage issuer ----
    auto issue = [&](int s, int buf) {
        const int tap = s / NCH, ch = s - tap * NCH;
        const int ky = tap / KS, kx = tap - ky * KS;
        const int hh = ah_ + ky - PH, ww = aw + kx - PH;
        const bool ok = (hh >= 0) && (hh < 32) && (ww >= 0) && (ww < 32);
        const size_t aoff = ok ? ((size_t)(((b << 5) + hh) * 32 + ww) * in_stride + ch * 32 + ac) : 0;
        const uint32_t sz = ok ? 16u : 0u;
        cpa16(smem_u32(&Ah[buf][ar][ac]), inH + aoff, sz);
        cpa16(smem_u32(&Al[buf][ar][ac]), inL + aoff, sz);
        const char* bu = wp + (size_t)(tap * NCH + ch) * unitB + (size_t)nofs * 64;
#pragma unroll
        for (int i = tid; i < OCT * 4; i += 256) {
            int rr = i >> 2, q = i & 3;
            cpa16(smem_u32(&Bh[buf][rr][q * 8]), bu + (size_t)i * 16, 16);
            cpa16(smem_u32(&Bl[buf][rr][q * 8]), bu + (size_t)OC * 64 + (size_t)i * 16, 16);
        }
        CP_COMMIT();
    };

    issue(0, 0);
    issue(1, 1);

    for (int s = 0; s < NST; s++) {
        const int buf = s & 1;
        if (s < NST - 1) CP_WAIT1(); else CP_WAIT0();
        __syncthreads();

        const uint32_t aAh = smem_u32(&Ah[buf][0][0]);
        const uint32_t aAl = smem_u32(&Al[buf][0][0]);
        const uint32_t aBh = smem_u32(&Bh[buf][0][0]);
        const uint32_t aBl = smem_u32(&Bl[buf][0][0]);

#pragma unroll
        for (int ks = 0; ks < 2; ks++) {
            uint32_t ahf[2][4], alf[2][4];
#pragma unroll
            for (int mt = 0; mt < 2; mt++) {
                uint32_t ro = (uint32_t)(wm * 32 + mt * 16 + (lane & 15)) * (LDA * 2)
                            + (uint32_t)(ks * 2 + (lane >> 4)) * 16;
                ldm4(ahf[mt], aAh + ro);
                ldm4(alf[mt], aAl + ro);
            }
            if (NT == 2) {
                uint32_t ro = (uint32_t)(wn * 16 + (lane & 15)) * (LDA * 2)
                            + (uint32_t)(ks * 2 + (lane >> 4)) * 16;
                uint32_t bh4[4], bl4[4];
                ldm4(bh4, aBh + ro);
                ldm4(bl4, aBl + ro);
#pragma unroll
                for (int sub = 0; sub < 2; sub++) {
#pragma unroll
                    for (int mt = 0; mt < 2; mt++) {
                        float* d = acc[mt][sub];
                        mma16816(d, ahf[mt], bh4[sub], bh4[sub + 2]);
                        mma16816(d, ahf[mt], bl4[sub], bl4[sub + 2]);
                        mma16816(d, alf[mt], bh4[sub], bh4[sub + 2]);
                    }
                }
            } else {
                uint32_t ro = (uint32_t)(wn * 8 + (lane & 7)) * (LDA * 2)
                            + (uint32_t)(ks * 2 + ((lane >> 3) & 1)) * 16;
                uint32_t bh2[2], bl2[2];
                ldm2(bh2, aBh + ro);
                ldm2(bl2, aBl + ro);
#pragma unroll
                for (int mt = 0; mt < 2; mt++) {
                    float* d = acc[mt][0];
                    mma16816(d, ahf[mt], bh2[0], bh2[1]);
                    mma16816(d, ahf[mt], bl2[0], bl2[1]);
                    mma16816(d, alf[mt], bh2[0], bh2[1]);
                }
            }
        }
        __syncthreads();
        if (s + 2 < NST) issue(s + 2, buf);
    }

    // ---- epilogue ----
    const int l4 = lane >> 2, l2 = (lane & 3) * 2;
#pragma unroll
    for (int nt = 0; nt < NT; nt++) {
        const int col = nofs + wn * (OCT / 4) + nt * 8 + l2;
        float b0 = 0.f, b1 = 0.f;
        if (bias) { b0 = bias[col]; b1 = bias[col + 1]; }
#pragma unroll
        for (int mt = 0; mt < 2; mt++) {
            const int pr = p0 + wm * 32 + mt * 16 + l4;
            float* d = acc[mt][nt];
            float v0 = d[0] + b0, v1 = d[1] + b1, v2 = d[2] + b0, v3 = d[3] + b1;
            if (RELU) {
                v0 = fmaxf(v0, 0.f); v1 = fmaxf(v1, 0.f);
                v2 = fmaxf(v2, 0.f); v3 = fmaxf(v3, 0.f);
            }
            if (ADDIN) {
                float2 a0 = *(const float2*)(addp + (size_t)pr * add_stride + col);
                float2 a1 = *(const float2*)(addp + (size_t)(pr + 8) * add_stride + col);
                v0 += a0.x; v1 += a0.y; v2 += a1.x; v3 += a1.y;
            }
            if (out) {
                *(float2*)(out + (size_t)pr * out_stride + col) = make_float2(v0, v1);
                *(float2*)(out + (size_t)(pr + 8) * out_stride + col) = make_float2(v2, v3);
            }
            __nv_bfloat162 h01 = __float22bfloat162_rn(make_float2(v0, v1));
            __nv_bfloat162 h23 = __float22bfloat162_rn(make_float2(v2, v3));
            float2 f01 = __bfloat1622float2(h01);
            float2 f23 = __bfloat1622float2(h23);
            __nv_bfloat162 l01 = __float22bfloat162_rn(make_float2(v0 - f01.x, v1 - f01.y));
            __nv_bfloat162 l23 = __float22bfloat162_rn(make_float2(v2 - f23.x, v3 - f23.y));
            *(__nv_bfloat162*)(outH + (size_t)pr * out_stride + col) = h01;
            *(__nv_bfloat162*)(outH + (size_t)(pr + 8) * out_stride + col) = h23;
            *(__nv_bfloat162*)(outL + (size_t)pr * out_stride + col) = l01;
            *(__nv_bfloat162*)(outL + (size_t)(pr + 8) * out_stride + col) = l23;
        }
    }
}

// ---------------- launch ----------------
extern "C" void kernel_launch(void* const* d_in, const int* in_sizes, int n_in,
                              void* d_out, int out_size) {
    const float* x     = (const float*)d_in[0];
    const float* mu    = (const float*)d_in[1];
    const float* sigma = (const float*)d_in[2];
    const float* wf    = (const float*)d_in[3];
    const float* bfl   = (const float*)d_in[4];
    const float* m     = (const float*)d_in[5];
    const int*   perm  = (const int*)d_in[6];
    float* out = (float*)d_out;

    char *wp, *mp;
    float *Xa, *Xb;
    __nv_bfloat16 *XaH, *XaL, *XbH, *XbL, *T1H, *T1L, *T2H, *T2L;
    cudaGetSymbolAddress((void**)&wp, g_wpc);
    cudaGetSymbolAddress((void**)&mp, g_mpc);
    cudaGetSymbolAddress((void**)&Xa, g_Xa);
    cudaGetSymbolAddress((void**)&Xb, g_Xb);
    cudaGetSymbolAddress((void**)&XaH, g_XaH);
    cudaGetSymbolAddress((void**)&XaL, g_XaL);
    cudaGetSymbolAddress((void**)&XbH, g_XbH);
    cudaGetSymbolAddress((void**)&XbL, g_XbL);
    cudaGetSymbolAddress((void**)&T1H, g_T1H);
    cudaGetSymbolAddress((void**)&T1L, g_T1L);
    cudaGetSymbolAddress((void**)&T2H, g_T2H);
    cudaGetSymbolAddress((void**)&T2L, g_T2L);

    k_wp<<<(WTOT + 255) / 256, 256>>>(wf);
    k_mp<<<(32 * 36864 + 255) / 256, 256>>>(m);
    k_pre<<<(NP * 192 + 255) / 256, 256>>>(x, mu, sigma, perm, Xa, XaH, XaL);

    const size_t pre_j[6] = {0, 442368, 1032192, 1474560, 1916928, 2506752};
    const int bstart[6] = {0, 128, 256, 352, 480, 608};

    float* X = Xa;  __nv_bfloat16 *XH = XaH, *XL = XaL;
    float* Y = Xb;  __nv_bfloat16 *YH = XbH, *YL = XbL;
    for (int blk = 0; blk < 32; blk++) {
        const char* wb = wp + (size_t)blk * WP_PER_BLK;
        const float* bb = bfl + blk * 704;
        // round 0: x1 += f0(x2)
        k_mma<96, 128, 64, 3, true, false><<<256, 256>>>(XH + 96, XL + 96, 192, wb + pre_j[0], bb + bstart[0], nullptr, 0, nullptr, T1H, T1L, 128);
        k_mma<128, 128, 64, 3, true, false><<<256, 256>>>(T1H, T1L, 128, wb + pre_j[1], bb + bstart[1], nullptr, 0, nullptr, T2H, T2L, 128);
        k_mma<128, 96, 32, 3, false, true><<<384, 256>>>(T2H, T2L, 128, wb + pre_j[2], bb + bstart[2], X + 0, 192, X + 0, XH + 0, XL + 0, 192);
        // round 1: x2 += f1(x1)
        k_mma<96, 128, 64, 3, true, false><<<256, 256>>>(XH + 0, XL + 0, 192, wb + pre_j[3], bb + bstart[3], nullptr, 0, nullptr, T1H, T1L, 128);
        k_mma<128, 128, 64, 3, true, false><<<256, 256>>>(T1H, T1L, 128, wb + pre_j[4], bb + bstart[4], nullptr, 0, nullptr, T2H, T2L, 128);
        k_mma<128, 96, 32, 3, false, true><<<384, 256>>>(T2H, T2L, 128, wb + pre_j[5], bb + bstart[5], X + 96, 192, X + 96, XH + 96, XL + 96, 192);
        // 1x1 mixing
        k_mma<192, 192, 64, 1, false, false><<<384, 256>>>(XH, XL, 192, mp + (size_t)blk * MP_PER_BLK, nullptr, nullptr, 0, Y, YH, YL, 192);
        float* tf = X; X = Y; Y = tf;
        __nv_bfloat16* th = XH; XH = YH; YH = th;
        __nv_bfloat16* tl = XL; XL = YL; YL = tl;
    }

    k_post<<<(NP * 192 + 255) / 256, 256>>>(X, out);
}

// round 5
// speedup vs baseline: 1.0890x; 1.0890x over previous
#include <cuda_runtime.h>
#include <cuda_bf16.h>
#include <cstdint>
#include <cstring>

// ---------------- constants ----------------
constexpr int NP = 8192;
constexpr int WTOT = 23592960;
constexpr int PER_BLK_W = 737280;
constexpr size_t WP_PER_BLK = 2949120;
constexpr size_t MP_PER_BLK = 147456;

// ---------------- device scratch ----------------
__device__ char g_wpc[32 * WP_PER_BLK];
__device__ char g_mpc[32 * MP_PER_BLK];
__device__ float g_Xa[NP * 192], g_Xb[NP * 192];
__device__ __nv_bfloat16 g_XaH[NP * 192], g_XaL[NP * 192];
__device__ __nv_bfloat16 g_XbH[NP * 192], g_XbL[NP * 192];
__device__ __nv_bfloat16 g_T1H[NP * 128], g_T1L[NP * 128];
__device__ __nv_bfloat16 g_T2H[NP * 128], g_T2L[NP * 128];

// ---------------- helpers ----------------
__device__ __forceinline__ uint32_t smem_u32(const void* p) {
    uint32_t a;
    asm("{ .reg .u64 t; cvta.to.shared.u64 t, %1; cvt.u32.u64 %0, t; }" : "=r"(a) : "l"(p));
    return a;
}
__device__ __forceinline__ unsigned short f2bf(float v) {
    __nv_bfloat16 b = __float2bfloat16(v);
    unsigned short u; memcpy(&u, &b, 2);
    return u;
}
__device__ __forceinline__ float bf2f(unsigned short u) {
    __nv_bfloat16 b; memcpy(&b, &u, 2);
    return __bfloat162float(b);
}
__device__ __forceinline__ void ldm4(uint32_t* r, uint32_t addr) {
    asm volatile("ldmatrix.sync.aligned.m8n8.x4.shared.b16 {%0,%1,%2,%3}, [%4];"
        : "=r"(r[0]), "=r"(r[1]), "=r"(r[2]), "=r"(r[3]) : "r"(addr));
}
__device__ __forceinline__ void ldm2(uint32_t* r, uint32_t addr) {
    asm volatile("ldmatrix.sync.aligned.m8n8.x2.shared.b16 {%0,%1}, [%2];"
        : "=r"(r[0]), "=r"(r[1]) : "r"(addr));
}
__device__ __forceinline__ void mma16816(float* d, const uint32_t* a, uint32_t b0, uint32_t b1) {
    asm volatile("mma.sync.aligned.m16n8k16.row.col.f32.bf16.bf16.f32 "
        "{%0,%1,%2,%3},{%4,%5,%6,%7},{%8,%9},{%0,%1,%2,%3};"
        : "+f"(d[0]), "+f"(d[1]), "+f"(d[2]), "+f"(d[3])
        : "r"(a[0]), "r"(a[1]), "r"(a[2]), "r"(a[3]), "r"(b0), "r"(b1));
}
__device__ __forceinline__ void cpa16(uint32_t dst, const void* src, uint32_t srcsz) {
    asm volatile("cp.async.cg.shared.global [%0], [%1], 16, %2;"
        :: "r"(dst), "l"(src), "r"(srcsz) : "memory");
}
#define CP_COMMIT() asm volatile("cp.async.commit_group;" ::: "memory")
#define CP_WAIT1()  asm volatile("cp.async.wait_group 1;" ::: "memory")

// ---------------- weight prepack (convs), dst-indexed ----------------
__global__ void k_wp(const float* __restrict__ wf) {
    int idx = blockIdx.x * 256 + threadIdx.x;
    if (idx >= WTOT) return;
    int blk = idx / PER_BLK_W;
    int r = idx - blk * PER_BLK_W;
    const int starts[6] = {0, 110592, 258048, 368640, 479232, 626688};
    const size_t pre[6] = {0, 442368, 1032192, 1474560, 1916928, 2506752};
    int j = 0;
#pragma unroll
    for (int t = 1; t < 6; t++) if (r >= starts[t]) j = t;
    int off = r - starts[j];
    int oc = ((j % 3) == 2) ? 96 : 128;
    int ic = ((j % 3) == 0) ? 96 : 128;
    int unitE = oc * 32;
    int u = off / unitE;
    int wi = off - u * unitE;
    int o = wi >> 5, cl = wi & 31;
    int nch = ic >> 5;
    int tap = u / nch, chk = u - tap * nch;
    int c = chk * 32 + cl;
    float v = wf[(size_t)blk * PER_BLK_W + starts[j] + (size_t)(o * ic + c) * 9 + tap];
    unsigned short hb = f2bf(v);
    unsigned short lb = f2bf(v - bf2f(hb));
    size_t base = (size_t)blk * WP_PER_BLK + pre[j] + (size_t)u * (oc * 128);
    *(unsigned short*)(g_wpc + base + (size_t)wi * 2) = hb;
    *(unsigned short*)(g_wpc + base + (size_t)oc * 64 + (size_t)wi * 2) = lb;
}

// ---------------- mixing prepack ----------------
__global__ void k_mp(const float* __restrict__ m) {
    int idx = blockIdx.x * 256 + threadIdx.x;
    if (idx >= 32 * 36864) return;
    int blk = idx / 36864;
    int r = idx - blk * 36864;
    int u = r / 6144;
    int wi = r - u * 6144;
    int o = wi >> 5, cl = wi & 31;
    int c = u * 32 + cl;
    float v = m[(size_t)blk * 36864 + o * 192 + c];
    unsigned short hb = f2bf(v);
    unsigned short lb = f2bf(v - bf2f(hb));
    size_t base = (size_t)blk * MP_PER_BLK + (size_t)u * 24576;
    *(unsigned short*)(g_mpc + base + (size_t)wi * 2) = hb;
    *(unsigned short*)(g_mpc + base + 12288 + (size_t)wi * 2) = lb;
}

// ---------------- normalize + permute + space_to_depth -> NHWC ----------------
__global__ void k_pre(const float* __restrict__ x, const float* __restrict__ mu,
                      const float* __restrict__ sigma, const int* __restrict__ perm,
                      float* __restrict__ Xo, __nv_bfloat16* __restrict__ XoH,
                      __nv_bfloat16* __restrict__ XoL) {
    int idx = blockIdx.x * 256 + threadIdx.x;
    if (idx >= NP * 192) return;
    int ch = idx % 192;
    int p = idx / 192;
    int w = p & 31, h = (p >> 5) & 31, b = p >> 10;
    int c = ch >> 6, r = ch & 63;
    int bi = r >> 3, bj = r & 7;
    int flat = (h * 8 + bi) * 256 + (w * 8 + bj);
    int src = perm[c * 65536 + flat];
    float v = (x[(b * 3 + c) * 65536 + src] - mu[c]) / sigma[c];
    Xo[idx] = v;
    unsigned short hb = f2bf(v);
    XoH[idx] = *(__nv_bfloat16*)&hb;
    unsigned short lb = f2bf(v - bf2f(hb));
    XoL[idx] = *(__nv_bfloat16*)&lb;
}

// ---------------- final NHWC -> NCHW ----------------
__global__ void k_post(const float* __restrict__ X, float* __restrict__ out) {
    int idx = blockIdx.x * 256 + threadIdx.x;
    if (idx >= NP * 192) return;
    int w = idx & 31;
    int h = (idx >> 5) & 31;
    int ch = (idx >> 10) % 192;
    int b = idx / (192 * 1024);
    out[idx] = X[(((b * 32 + h) * 32 + w) * 192) + ch];
}

// ---------------- warp-mma bf16x3 implicit-GEMM conv ----------------
// CTA = 64 positions x full OC. 8 warps: wm = wid&1 (two m16 tiles),
// wn = wid>>1 (OC/4 columns). Triple-buffered cp.async, 1 sync/stage.
template <int IC, int OC, int KS, bool RELU, bool ADDIN>
__global__ __launch_bounds__(256) void k_mma(
    const __nv_bfloat16* __restrict__ inH, const __nv_bfloat16* __restrict__ inL,
    int in_stride,
    const char* __restrict__ wp,
    const float* __restrict__ bias,
    const float* __restrict__ addp, int add_stride,
    float* __restrict__ out,
    __nv_bfloat16* __restrict__ outH, __nv_bfloat16* __restrict__ outL,
    int out_stride)
{
    constexpr int NCH = IC / 32;
    constexpr int NST = KS * KS * NCH;
    constexpr int NT = OC / 32;          // n8-tile pairs basis (warp N = OC/4)
    constexpr int PH = KS / 2;
    constexpr int LDA = 40;              // padded bf16 row stride (80 B)
    constexpr int ASZ = 64 * LDA;        // ush per A buffer
    constexpr int BSZ = OC * LDA;        // ush per B buffer
    constexpr int unitB = OC * 128;

    extern __shared__ __align__(16) unsigned short smem[];
    unsigned short* Ah = smem;                 // [3][64][LDA]
    unsigned short* Al = Ah + 3 * ASZ;
    unsigned short* Bh = Al + 3 * ASZ;         // [3][OC][LDA]
    unsigned short* Bl = Bh + 3 * BSZ;

    const int tid = threadIdx.x;
    const int wid = tid >> 5, lane = tid & 31;
    const int wm = wid & 1, wn = wid >> 1;
    const int p0 = blockIdx.x * 64;
    const int b = p0 >> 10;
    const int h0 = (p0 >> 5) & 31;

    // A staging map: thread -> (row 0..63, 8-channel quad)
    const int ar = tid >> 2;
    const int ac = (tid & 3) * 8;
    const int ah_ = h0 + (ar >> 5);
    const int aw = ar & 31;

    float acc[2][NT][4];
#pragma unroll
    for (int i = 0; i < 2; i++)
#pragma unroll
        for (int j = 0; j < NT; j++)
#pragma unroll
            for (int q = 0; q < 4; q++) acc[i][j][q] = 0.f;

    // hoisted staging addresses
    const uint32_t sAh = smem_u32(Ah) + (uint32_t)(ar * LDA + ac) * 2;
    const uint32_t sAl = smem_u32(Al) + (uint32_t)(ar * LDA + ac) * 2;
    const uint32_t sBh = smem_u32(Bh);
    const uint32_t sBl = smem_u32(Bl);

    auto issue = [&](int s, int buf) {
        const int tap = s / NCH, ch = s - tap * NCH;
        const int ky = tap / KS, kx = tap - ky * KS;
        const int hh = ah_ + ky - PH, ww = aw + kx - PH;
        const bool ok = (hh >= 0) && (hh < 32) && (ww >= 0) && (ww < 32);
        const size_t aoff = ok ? ((size_t)(((b << 5) + hh) * 32 + ww) * in_stride + ch * 32 + ac) : 0;
        const uint32_t sz = ok ? 16u : 0u;
        cpa16(sAh + (uint32_t)buf * ASZ * 2, inH + aoff, sz);
        cpa16(sAl + (uint32_t)buf * ASZ * 2, inL + aoff, sz);
        const char* bu = wp + (size_t)s * unitB;
#pragma unroll
        for (int i = tid; i < OC * 4; i += 256) {
            int rr = i >> 2, q = i & 3;
            uint32_t doff = (uint32_t)(buf * BSZ + rr * LDA + q * 8) * 2;
            cpa16(sBh + doff, bu + (size_t)i * 16, 16);
            cpa16(sBl + doff, bu + (size_t)OC * 64 + (size_t)i * 16, 16);
        }
        CP_COMMIT();
    };

    issue(0, 0);
    issue(1, 1);

    for (int s = 0; s < NST; s++) {
        const int buf0 = s - (s / 3) * 3;
        CP_WAIT1();
        __syncthreads();
        if (s + 2 < NST) {
            int b2 = (s + 2) - ((s + 2) / 3) * 3;
            issue(s + 2, b2);
        } else {
            CP_COMMIT();
        }

        const uint32_t aAh = smem_u32(Ah + buf0 * ASZ);
        const uint32_t aAl = smem_u32(Al + buf0 * ASZ);
        const uint32_t aBh = smem_u32(Bh + buf0 * BSZ);
        const uint32_t aBl = smem_u32(Bl + buf0 * BSZ);

#pragma unroll
        for (int ks = 0; ks < 2; ks++) {
            uint32_t ahf[2][4], alf[2][4];
#pragma unroll
            for (int mt = 0; mt < 2; mt++) {
                uint32_t ro = (uint32_t)(wm * 32 + mt * 16 + (lane & 15)) * (LDA * 2)
                            + (uint32_t)(ks * 2 + (lane >> 4)) * 16;
                ldm4(ahf[mt], aAh + ro);
                ldm4(alf[mt], aAl + ro);
            }
#pragma unroll
            for (int np = 0; np < NT / 2; np++) {
                uint32_t ro = (uint32_t)(wn * (OC / 4) + np * 16 + (lane & 15)) * (LDA * 2)
                            + (uint32_t)(ks * 2 + (lane >> 4)) * 16;
                uint32_t bh4[4], bl4[4];
                ldm4(bh4, aBh + ro);
                ldm4(bl4, aBl + ro);
#pragma unroll
                for (int sub = 0; sub < 2; sub++) {
#pragma unroll
                    for (int mt = 0; mt < 2; mt++) {
                        float* d = acc[mt][np * 2 + sub];
                        mma16816(d, ahf[mt], bh4[sub], bh4[sub + 2]);
                        mma16816(d, ahf[mt], bl4[sub], bl4[sub + 2]);
                        mma16816(d, alf[mt], bh4[sub], bh4[sub + 2]);
                    }
                }
            }
            if (NT & 1) {
                uint32_t ro = (uint32_t)(wn * (OC / 4) + (NT - 1) * 8 + (lane & 7)) * (LDA * 2)
                            + (uint32_t)(ks * 2 + ((lane >> 3) & 1)) * 16;
                uint32_t bh2[2], bl2[2];
                ldm2(bh2, aBh + ro);
                ldm2(bl2, aBl + ro);
#pragma unroll
                for (int mt = 0; mt < 2; mt++) {
                    float* d = acc[mt][NT - 1];
                    mma16816(d, ahf[mt], bh2[0], bh2[1]);
                    mma16816(d, ahf[mt], bl2[0], bl2[1]);
                    mma16816(d, alf[mt], bh2[0], bh2[1]);
                }
            }
        }
    }

    // ---- epilogue ----
    const int l4 = lane >> 2, l2 = (lane & 3) * 2;
#pragma unroll
    for (int nt = 0; nt < NT; nt++) {
        const int col = wn * (OC / 4) + nt * 8 + l2;
        float b0 = 0.f, b1 = 0.f;
        if (bias) { b0 = bias[col]; b1 = bias[col + 1]; }
#pragma unroll
        for (int mt = 0; mt < 2; mt++) {
            const int pr = p0 + wm * 32 + mt * 16 + l4;
            float* d = acc[mt][nt];
            float v0 = d[0] + b0, v1 = d[1] + b1, v2 = d[2] + b0, v3 = d[3] + b1;
            if (RELU) {
                v0 = fmaxf(v0, 0.f); v1 = fmaxf(v1, 0.f);
                v2 = fmaxf(v2, 0.f); v3 = fmaxf(v3, 0.f);
            }
            if (ADDIN) {
                float2 a0 = *(const float2*)(addp + (size_t)pr * add_stride + col);
                float2 a1 = *(const float2*)(addp + (size_t)(pr + 8) * add_stride + col);
                v0 += a0.x; v1 += a0.y; v2 += a1.x; v3 += a1.y;
            }
            if (out) {
                *(float2*)(out + (size_t)pr * out_stride + col) = make_float2(v0, v1);
                *(float2*)(out + (size_t)(pr + 8) * out_stride + col) = make_float2(v2, v3);
            }
            __nv_bfloat162 h01 = __float22bfloat162_rn(make_float2(v0, v1));
            __nv_bfloat162 h23 = __float22bfloat162_rn(make_float2(v2, v3));
            float2 f01 = __bfloat1622float2(h01);
            float2 f23 = __bfloat1622float2(h23);
            __nv_bfloat162 l01 = __float22bfloat162_rn(make_float2(v0 - f01.x, v1 - f01.y));
            __nv_bfloat162 l23 = __float22bfloat162_rn(make_float2(v2 - f23.x, v3 - f23.y));
            *(__nv_bfloat162*)(outH + (size_t)pr * out_stride + col) = h01;
            *(__nv_bfloat162*)(outH + (size_t)(pr + 8) * out_stride + col) = h23;
            *(__nv_bfloat162*)(outL + (size_t)pr * out_stride + col) = l01;
            *(__nv_bfloat162*)(outL + (size_t)(pr + 8) * out_stride + col) = l23;
        }
    }
}

// ---------------- launch ----------------
extern "C" void kernel_launch(void* const* d_in, const int* in_sizes, int n_in,
                              void* d_out, int out_size) {
    const float* x     = (const float*)d_in[0];
    const float* mu    = (const float*)d_in[1];
    const float* sigma = (const float*)d_in[2];
    const float* wf    = (const float*)d_in[3];
    const float* bfl   = (const float*)d_in[4];
    const float* m     = (const float*)d_in[5];
    const int*   perm  = (const int*)d_in[6];
    float* out = (float*)d_out;

    char *wp, *mp;
    float *Xa, *Xb;
    __nv_bfloat16 *XaH, *XaL, *XbH, *XbL, *T1H, *T1L, *T2H, *T2L;
    cudaGetSymbolAddress((void**)&wp, g_wpc);
    cudaGetSymbolAddress((void**)&mp, g_mpc);
    cudaGetSymbolAddress((void**)&Xa, g_Xa);
    cudaGetSymbolAddress((void**)&Xb, g_Xb);
    cudaGetSymbolAddress((void**)&XaH, g_XaH);
    cudaGetSymbolAddress((void**)&XaL, g_XaL);
    cudaGetSymbolAddress((void**)&XbH, g_XbH);
    cudaGetSymbolAddress((void**)&XbL, g_XbL);
    cudaGetSymbolAddress((void**)&T1H, g_T1H);
    cudaGetSymbolAddress((void**)&T1L, g_T1L);
    cudaGetSymbolAddress((void**)&T2H, g_T2H);
    cudaGetSymbolAddress((void**)&T2L, g_T2L);

    // dynamic smem: 480 * (64 + OC) bytes
    const int SM128 = 480 * (64 + 128);   // 92160
    const int SM96  = 480 * (64 + 96);    // 76800
    const int SM192 = 480 * (64 + 192);   // 122880
    static bool attr_done = false;
    if (!attr_done) {
        cudaFuncSetAttribute(k_mma<96, 128, 3, true, false>,  cudaFuncAttributeMaxDynamicSharedMemorySize, SM128);
        cudaFuncSetAttribute(k_mma<128, 128, 3, true, false>, cudaFuncAttributeMaxDynamicSharedMemorySize, SM128);
        cudaFuncSetAttribute(k_mma<128, 96, 3, false, true>,  cudaFuncAttributeMaxDynamicSharedMemorySize, SM96);
        cudaFuncSetAttribute(k_mma<192, 192, 1, false, false>, cudaFuncAttributeMaxDynamicSharedMemorySize, SM192);
        attr_done = true;
    }

    k_wp<<<(WTOT + 255) / 256, 256>>>(wf);
    k_mp<<<(32 * 36864 + 255) / 256, 256>>>(m);
    k_pre<<<(NP * 192 + 255) / 256, 256>>>(x, mu, sigma, perm, Xa, XaH, XaL);

    const size_t pre_j[6] = {0, 442368, 1032192, 1474560, 1916928, 2506752};
    const int bstart[6] = {0, 128, 256, 352, 480, 608};

    float* X = Xa;  __nv_bfloat16 *XH = XaH, *XL = XaL;
    float* Y = Xb;  __nv_bfloat16 *YH = XbH, *YL = XbL;
    for (int blk = 0; blk < 32; blk++) {
        const char* wb = wp + (size_t)blk * WP_PER_BLK;
        const float* bb = bfl + blk * 704;
        // round 0: x1 += f0(x2)
        k_mma<96, 128, 3, true, false><<<128, 256, SM128>>>(XH + 96, XL + 96, 192, wb + pre_j[0], bb + bstart[0], nullptr, 0, nullptr, T1H, T1L, 128);
        k_mma<128, 128, 3, true, false><<<128, 256, SM128>>>(T1H, T1L, 128, wb + pre_j[1], bb + bstart[1], nullptr, 0, nullptr, T2H, T2L, 128);
        k_mma<128, 96, 3, false, true><<<128, 256, SM96>>>(T2H, T2L, 128, wb + pre_j[2], bb + bstart[2], X + 0, 192, X + 0, XH + 0, XL + 0, 192);
        // round 1: x2 += f1(x1)
        k_mma<96, 128, 3, true, false><<<128, 256, SM128>>>(XH + 0, XL + 0, 192, wb + pre_j[3], bb + bstart[3], nullptr, 0, nullptr, T1H, T1L, 128);
        k_mma<128, 128, 3, true, false><<<128, 256, SM128>>>(T1H, T1L, 128, wb + pre_j[4], bb + bstart[4], nullptr, 0, nullptr, T2H, T2L, 128);
        k_mma<128, 96, 3, false, true><<<128, 256, SM96>>>(T2H, T2L, 128, wb + pre_j[5], bb + bstart[5], X + 96, 192, X + 96, XH + 96, XL + 96, 192);
        // 1x1 mixing
        k_mma<192, 192, 1, false, false><<<128, 256, SM192>>>(XH, XL, 192, mp + (size_t)blk * MP_PER_BLK, nullptr, nullptr, 0, Y, YH, YL, 192);
        float* tf = X; X = Y; Y = tf;
        __nv_bfloat16* th = XH; XH = YH; YH = th;
        __nv_bfloat16* tl = XL; XL = YL; YL = tl;
    }

    k_post<<<(NP * 192 + 255) / 256, 256>>>(X, out);
}